// round 15
// baseline (speedup 1.0000x reference)
#include <cuda_runtime.h>
#include <cstdint>

typedef unsigned long long u64;
typedef unsigned int u32;

#define NUM_BITS 16
#define THETA 8
#define HN 4096
#define FF 128
#define CC 10
#define BB 64
#define P0 2048                      // F*NUM_BITS
#define SEGS_PER_LAYER (2 * HN)      // 8192
#define HALF_SEGS (SEGS_PER_LAYER / 2)
#define TOT_SEGS (3 * SEGS_PER_LAYER)
#define SEGW 4                       // u64 words per (segment, lane)

#define OUT_BLOCKS 192
#define LH_PER_BLOCK 64              // 12288 / 192

// Scratch (device globals: no allocation allowed in kernel_launch)
__device__ u64 g_act[P0];                    // layer-0 input masks
__device__ u64 g_fired[3 * HN];              // per-layer fired masks
__device__ u64 g_hits[(size_t)TOT_SEGS * 32 * SEGW];  // presLo,presHi,sgnLo,sgnHi
__device__ float g_part[OUT_BLOCKS * BB * CC];

// -------------------------------------------------------------------------
// Encode: x[B,F] -> g_act[p], p = f*16 + t, bit b = (x[b,f] >= (t+1)/17)
// -------------------------------------------------------------------------
__global__ void encode_kernel(const float* __restrict__ x) {
    int p = blockIdx.x * blockDim.x + threadIdx.x;
    if (p >= P0) return;
    int f = p >> 4;
    int t = p & 15;
    float thr = (float)(t + 1) / (float)(NUM_BITS + 1);
    u64 m = 0ull;
#pragma unroll
    for (int b = 0; b < BB; b++) {
        float v = __ldg(&x[b * FF + f]);
        m |= ((u64)(v >= thr)) << b;
    }
    g_act[p] = m;
}

// -------------------------------------------------------------------------
// Extract: one warp per SEGMENT (grid-sliced). Rolling 8-deep uint4
// pipeline. Per 16B step: build a 4-bit nonzero nibble + 4-bit sign nibble
// and OR them into per-lane presence/sign bitmaps at a compile-time shift.
// ZERO branches, ZERO stores, ZERO warp collectives in the loop. Bit
// k = step*4 + j  <->  position (k>>2)*128 + lane*4 + (k&3).
// End: 2 coalesced 16B stores per lane (1KB contiguous per warp).
// Exact (any hit count), deterministic.
// -------------------------------------------------------------------------
template <int P>
__global__ __launch_bounds__(256) void extract_kernel(
    const float* __restrict__ W, int segbase, int segstart) {
    int seg = segstart + ((blockIdx.x * blockDim.x + threadIdx.x) >> 5);
    int lane = threadIdx.x & 31;

    const uint4* row = (const uint4*)(W + (size_t)seg * (size_t)P);
    u64 pl = 0, ph = 0, sl = 0, sh = 0;

    constexpr int NS = P / 128;       // uint4 steps per lane: 16 or 32
    uint4 v[8];
#pragma unroll
    for (int k = 0; k < 8; k++)
        v[k] = __ldg(&row[k * 32 + lane]);

#pragma unroll
    for (int i = 0; i < NS; i++) {
        uint4 w = v[i & 7];
        if (i + 8 < NS)                       // refill behind processing
            v[i & 7] = __ldg(&row[(i + 8) * 32 + lane]);

        u32 nz = (u32)(w.x != 0u) | ((u32)(w.y != 0u) << 1)
               | ((u32)(w.z != 0u) << 2) | ((u32)(w.w != 0u) << 3);
        u32 sg = (w.x >> 31) | ((w.y >> 31) << 1)
               | ((w.z >> 31) << 2) | ((w.w >> 31) << 3);
        if (i < 16) {                         // compile-time under unroll
            pl |= (u64)nz << (4 * i);
            sl |= (u64)sg << (4 * i);
        } else {
            ph |= (u64)nz << (4 * (i - 16));
            sh |= (u64)sg << (4 * (i - 16));
        }
    }

    ulonglong2* out =
        (ulonglong2*)&g_hits[((size_t)(segbase + seg) * 32 + lane) * SEGW];
    out[0] = make_ulonglong2(pl, ph);
    out[1] = make_ulonglong2(sl, sh);
}

// -------------------------------------------------------------------------
// Fire: one warp per NEURON. Per segment, each lane loads its 32B bitmap
// (2x LDG.128), ffs-walks its set bits (avg 1/lane), decodes the position
// arithmetically, and accumulates +-act masks into 7-plane signed
// bit-sliced counters over 64 batches (two's complement, bounded +-32 ->
// exact). 5-round butterfly; fired iff count>=8 (sign clear & bits 3..5).
// Order-free integer math -> deterministic.
// -------------------------------------------------------------------------
__device__ __forceinline__ void acc_hit(u64* c, u64 m, u64 neg) {
    u64 a = m, carry = 0;
#pragma unroll
    for (int k = 0; k < 7; k++) {
        u64 ck = c[k];
        u64 x = ck ^ a;
        c[k] = x ^ carry;
        carry = (ck & a) | (carry & x);
        a = m & neg;   // planes 1..6: 0 for +1, m for -1
    }
}

__device__ __forceinline__ u64 fire_segment(int seg, int lane,
                                            const u64* __restrict__ act) {
    const ulonglong2* sp =
        (const ulonglong2*)&g_hits[((size_t)seg * 32 + lane) * SEGW];
    ulonglong2 pq = __ldg(&sp[0]);   // presLo, presHi
    ulonglong2 sq = __ldg(&sp[1]);   // sgnLo,  sgnHi

    u64 c[7] = {0, 0, 0, 0, 0, 0, 0};
    int lbase = lane * 4;

    u64 pres = pq.x;
    while (pres) {
        int k = __ffsll(pres) - 1;
        pres &= pres - 1;
        int pos = (k >> 2) * 128 + lbase + (k & 3);
        u64 m = __ldg(&act[pos]);
        u64 neg = (u64)0 - ((sq.x >> k) & 1ull);
        acc_hit(c, m, neg);
    }
    pres = pq.y;
    while (pres) {
        int k = __ffsll(pres) - 1;
        pres &= pres - 1;
        int pos = ((k >> 2) + 16) * 128 + lbase + (k & 3);
        u64 m = __ldg(&act[pos]);
        u64 neg = (u64)0 - ((sq.y >> k) & 1ull);
        acc_hit(c, m, neg);
    }

    // bit-sliced butterfly across lanes
#pragma unroll
    for (int off = 16; off > 0; off >>= 1) {
        u64 t[7];
#pragma unroll
        for (int k = 0; k < 7; k++)
            t[k] = __shfl_xor_sync(0xffffffffu, c[k], off);
        u64 carry = 0;
#pragma unroll
        for (int k = 0; k < 7; k++) {
            u64 ck = c[k], bk = t[k];
            u64 x = ck ^ bk;
            c[k] = x ^ carry;
            carry = (ck & bk) | (carry & x);
        }
    }
    return ~c[6] & (c[3] | c[4] | c[5]);
}

__global__ __launch_bounds__(256) void fire_kernel(
    const u64* __restrict__ act, int segbase, u64* __restrict__ fired) {
    int h = (blockIdx.x * blockDim.x + threadIdx.x) >> 5;
    int lane = threadIdx.x & 31;
    if (h >= HN) return;

    u64 fm = fire_segment(segbase + 2 * h, lane, act);
    fm |= fire_segment(segbase + 2 * h + 1, lane, act);
    if (lane == 0) fired[h] = fm;
}

// -------------------------------------------------------------------------
// Output stage 1: partial sums over [lhstart, lhstart + blocks*64) slices.
// -------------------------------------------------------------------------
__global__ __launch_bounds__(640) void out_partial_kernel(
    const float* __restrict__ oW,
    const u64* __restrict__ fired,
    float* __restrict__ part, int lhstart, int partblock0) {
    int t = threadIdx.x;          // 0..639
    int b = t & 63;
    int c = t >> 6;
    int start = lhstart + blockIdx.x * LH_PER_BLOCK;
    float acc = 0.0f;
#pragma unroll 16
    for (int i = 0; i < LH_PER_BLOCK; i++) {
        int lh = start + i;
        u64 m = __ldg(&fired[lh]);
        float w = __ldg(&oW[lh * CC + c]);
        acc += w * (float)((m >> b) & 1ull);
    }
    part[(partblock0 + blockIdx.x) * (BB * CC) + t] = acc;
}

// Output stage 2: deterministic fixed-order reduction of partials.
__global__ void out_reduce_kernel(const float* __restrict__ part,
                                  float* __restrict__ out) {
    int t = threadIdx.x;
    if (t >= BB * CC) return;
    float s = 0.0f;
#pragma unroll
    for (int k = 0; k < OUT_BLOCKS; k++) s += part[k * (BB * CC) + t];
    int b = t & 63;
    int c = t >> 6;
    out[b * CC + c] = s;
}

// -------------------------------------------------------------------------
// Launch: R12's 3-stream schedule (best so far) captured into the graph.
//   s0: ex0a -> ex1a -> ex2a
//   s1: ex0b -> ex1b -> ex2b
//   s2: encode -> fire0 -> fire1 -> out01 -> fire2 -> out2 -> reduce
// out01 (layers 0,1) hides under extraction; tail is fire2+out2+reduce.
// Streams/events created ONCE on the first (pre-capture) call and reused —
// per-call creation leaked stream-pool memory past teardown (R10 fail).
// -------------------------------------------------------------------------
extern "C" void kernel_launch(void* const* d_in, const int* in_sizes, int n_in,
                              void* d_out, int out_size) {
    const float* x  = (const float*)d_in[0];
    const float* W0 = (const float*)d_in[1];
    const float* W1 = (const float*)d_in[2];
    const float* W2 = (const float*)d_in[3];
    const float* oW = (const float*)d_in[4];
    float* out = (float*)d_out;

    u64* act = nullptr;
    u64* fired = nullptr;
    float* part = nullptr;
    cudaGetSymbolAddress((void**)&act, g_act);
    cudaGetSymbolAddress((void**)&fired, g_fired);
    cudaGetSymbolAddress((void**)&part, g_part);

    static cudaStream_t s1 = nullptr, s2 = nullptr;
    static cudaEvent_t eFork, eA0, eA1, eA2, eB0, eB1, eB2, eDone;
    if (s1 == nullptr) {
        cudaStreamCreateWithFlags(&s1, cudaStreamNonBlocking);
        cudaStreamCreateWithFlags(&s2, cudaStreamNonBlocking);
        cudaEventCreateWithFlags(&eFork, cudaEventDisableTiming);
        cudaEventCreateWithFlags(&eA0, cudaEventDisableTiming);
        cudaEventCreateWithFlags(&eA1, cudaEventDisableTiming);
        cudaEventCreateWithFlags(&eA2, cudaEventDisableTiming);
        cudaEventCreateWithFlags(&eB0, cudaEventDisableTiming);
        cudaEventCreateWithFlags(&eB1, cudaEventDisableTiming);
        cudaEventCreateWithFlags(&eB2, cudaEventDisableTiming);
        cudaEventCreateWithFlags(&eDone, cudaEventDisableTiming);
    }

    // fork side streams into the capture
    cudaEventRecord(eFork, 0);
    cudaStreamWaitEvent(s1, eFork, 0);
    cudaStreamWaitEvent(s2, eFork, 0);

    // s2: encode early (only gates fire0)
    encode_kernel<<<(P0 + 255) / 256, 256, 0, s2>>>(x);

    // s0/s1: half-grids of each layer's extract, in layer order
    extract_kernel<P0><<<512, 256>>>(W0, 0, 0);
    extract_kernel<P0><<<512, 256, 0, s1>>>(W0, 0, HALF_SEGS);
    cudaEventRecord(eA0, 0);
    cudaEventRecord(eB0, s1);

    extract_kernel<HN><<<512, 256>>>(W1, SEGS_PER_LAYER, 0);
    extract_kernel<HN><<<512, 256, 0, s1>>>(W1, SEGS_PER_LAYER, HALF_SEGS);
    cudaEventRecord(eA1, 0);
    cudaEventRecord(eB1, s1);

    extract_kernel<HN><<<512, 256>>>(W2, 2 * SEGS_PER_LAYER, 0);
    extract_kernel<HN><<<512, 256, 0, s1>>>(W2, 2 * SEGS_PER_LAYER, HALF_SEGS);
    cudaEventRecord(eA2, 0);
    cudaEventRecord(eB2, s1);

    // s2: fire chain + output, gated per layer
    cudaStreamWaitEvent(s2, eA0, 0);
    cudaStreamWaitEvent(s2, eB0, 0);
    fire_kernel<<<512, 256, 0, s2>>>(act, 0, fired);
    cudaStreamWaitEvent(s2, eA1, 0);
    cudaStreamWaitEvent(s2, eB1, 0);
    fire_kernel<<<512, 256, 0, s2>>>(fired, SEGS_PER_LAYER, fired + HN);
    out_partial_kernel<<<128, BB * CC, 0, s2>>>(oW, fired, part, 0, 0);
    cudaStreamWaitEvent(s2, eA2, 0);
    cudaStreamWaitEvent(s2, eB2, 0);
    fire_kernel<<<512, 256, 0, s2>>>(fired + HN, 2 * SEGS_PER_LAYER,
                                     fired + 2 * HN);
    out_partial_kernel<<<64, BB * CC, 0, s2>>>(oW, fired, part,
                                               2 * HN, 128);
    out_reduce_kernel<<<1, BB * CC, 0, s2>>>(part, out);

    // join everything back into the origin stream (single graph sink)
    cudaEventRecord(eDone, s2);
    cudaStreamWaitEvent(0, eDone, 0);
}

// round 16
// speedup vs baseline: 1.0583x; 1.0583x over previous
#include <cuda_runtime.h>
#include <cstdint>

typedef unsigned long long u64;
typedef unsigned int u32;

#define NUM_BITS 16
#define THETA 8
#define HN 4096
#define FF 128
#define CC 10
#define BB 64
#define P0 2048                      // F*NUM_BITS
#define SEGS_PER_LAYER (2 * HN)      // 8192
#define TOT_SEGS (3 * SEGS_PER_LAYER)
#define MAXH 32

#define OUT_BLOCKS 192
#define LH_PER_BLOCK 64              // 12288 / 192

// Scratch (device globals: no allocation allowed in kernel_launch)
__device__ u64 g_act[P0];                 // layer-0 input masks
__device__ u64 g_fired[3 * HN];           // per-layer fired masks
__device__ u32 g_cnt[TOT_SEGS];           // entries per segment (<= 32)
__device__ u64 g_hits[TOT_SEGS * MAXH];   // packed: 4 x 16b (pos|sign|valid)
__device__ float g_part[OUT_BLOCKS * BB * CC];

// -------------------------------------------------------------------------
// Encode: x[B,F] -> g_act[p], p = f*16 + t, bit b = (x[b,f] >= (t+1)/17)
// -------------------------------------------------------------------------
__global__ void encode_kernel(const float* __restrict__ x) {
    int p = blockIdx.x * blockDim.x + threadIdx.x;
    if (p >= P0) return;
    int f = p >> 4;
    int t = p & 15;
    float thr = (float)(t + 1) / (float)(NUM_BITS + 1);
    u64 m = 0ull;
#pragma unroll
    for (int b = 0; b < BB; b++) {
        float v = __ldg(&x[b * FF + f]);
        m |= ((u64)(v >= thr)) << b;
    }
    g_act[p] = m;
}

// -------------------------------------------------------------------------
// Extract (R12 kernel, full-layer grid): one warp per SEGMENT. Rolling
// 8-deep uint4 pipeline. ONE ballot per 16B step: hitting lanes pack their
// component hits into a single u64 entry
//   field j (16b) = pos(12b) | signbit<<12 | valid<<13
// stored at base + popc(bal & ltmask). base advances warp-uniformly.
// Deterministic, no atomics. Entries per segment <= nonzeros <= 32.
// -------------------------------------------------------------------------
__device__ __forceinline__ u32 enc_hit(u32 wb, int p) {
    return wb ? ((u32)p | ((wb >> 31) << 12) | (1u << 13)) : 0u;
}

template <int P>
__global__ __launch_bounds__(256) void extract_kernel(
    const float* __restrict__ W, int segbase) {
    int seg = (blockIdx.x * blockDim.x + threadIdx.x) >> 5;   // 0..8191
    int lane = threadIdx.x & 31;
    u32 ltmask = (1u << lane) - 1u;

    const uint4* row = (const uint4*)(W + (size_t)seg * (size_t)P);
    u64* hp = &g_hits[(size_t)(segbase + seg) * MAXH];
    int base = 0;

    constexpr int NS = P / 128;       // uint4 steps per lane: 16 or 32
    uint4 v[8];
#pragma unroll
    for (int k = 0; k < 8; k++)
        v[k] = __ldg(&row[k * 32 + lane]);

#pragma unroll
    for (int i = 0; i < NS; i++) {
        uint4 w = v[i & 7];
        if (i + 8 < NS)                       // refill slot behind processing
            v[i & 7] = __ldg(&row[(i + 8) * 32 + lane]);

        u32 any = (w.x | w.y) | (w.z | w.w);
        u32 bal = __ballot_sync(0xffffffffu, any != 0u);
        if (bal) {                            // warp-uniform branch
            if (any) {                        // ~1 lane per step
                int p = (i * 32 + lane) * 4;
                u64 e = (u64)enc_hit(w.x, p)
                      | ((u64)enc_hit(w.y, p + 1) << 16)
                      | ((u64)enc_hit(w.z, p + 2) << 32)
                      | ((u64)enc_hit(w.w, p + 3) << 48);
                int s = base + __popc(bal & ltmask);
                if (s < MAXH) hp[s] = e;
            }
            base += __popc(bal);
        }
    }
    if (lane == 0)
        g_cnt[segbase + seg] = (u32)(base > MAXH ? MAXH : base);
}

// -------------------------------------------------------------------------
// Fire (R12): one warp per NEURON. Lane k loads packed entry k of each
// segment (parallel). Decodes <=4 sub-hits, accumulates +-act masks into
// 7-plane signed bit-sliced counters (two's complement, bounded +-32 ->
// exact). One 5-round butterfly per segment; fired iff count>=8 (sign
// clear and any of bits 3..5). Deterministic.
// -------------------------------------------------------------------------
__device__ __forceinline__ void acc_entry(u64 e, const u64* __restrict__ act,
                                          u64* c) {
#pragma unroll
    for (int j = 0; j < 4; j++) {
        u32 f = (u32)(e >> (16 * j)) & 0xFFFFu;
        if (f & (1u << 13)) {
            u64 m = __ldg(&act[f & 0xFFFu]);
            u64 neg = (f & (1u << 12)) ? ~0ull : 0ull;
            u64 a = m, carry = 0;
#pragma unroll
            for (int k = 0; k < 7; k++) {
                u64 ck = c[k];
                u64 x = ck ^ a;
                c[k] = x ^ carry;
                carry = (ck & a) | (carry & x);
                a = m & neg;   // planes 1..6: 0 for +1, m for -1
            }
        }
    }
}

__device__ __forceinline__ u64 reduce_fire(u64* c) {
#pragma unroll
    for (int off = 16; off > 0; off >>= 1) {
        u64 t[7];
#pragma unroll
        for (int k = 0; k < 7; k++)
            t[k] = __shfl_xor_sync(0xffffffffu, c[k], off);
        u64 carry = 0;
#pragma unroll
        for (int k = 0; k < 7; k++) {
            u64 ck = c[k], bk = t[k];
            u64 x = ck ^ bk;
            c[k] = x ^ carry;
            carry = (ck & bk) | (carry & x);
        }
    }
    return ~c[6] & (c[3] | c[4] | c[5]);
}

__global__ __launch_bounds__(256) void fire_kernel(
    const u64* __restrict__ act, int segbase, u64* __restrict__ fired) {
    int h = (blockIdx.x * blockDim.x + threadIdx.x) >> 5;
    int lane = threadIdx.x & 31;
    if (h >= HN) return;

    int seg0 = segbase + 2 * h;
    int n0 = (int)g_cnt[seg0];
    int n1 = (int)g_cnt[seg0 + 1];

    u64 e0 = (lane < n0) ? __ldg(&g_hits[(size_t)seg0 * MAXH + lane]) : 0ull;
    u64 e1 = (lane < n1) ? __ldg(&g_hits[(size_t)(seg0 + 1) * MAXH + lane])
                         : 0ull;

    u64 c[7] = {0, 0, 0, 0, 0, 0, 0};
    acc_entry(e0, act, c);
    u64 fm = reduce_fire(c);
#pragma unroll
    for (int k = 0; k < 7; k++) c[k] = 0ull;
    acc_entry(e1, act, c);
    fm |= reduce_fire(c);

    if (lane == 0) fired[h] = fm;
}

// -------------------------------------------------------------------------
// Output stage 1: partial sums over [lhstart, lhstart + blocks*64) slices.
// -------------------------------------------------------------------------
__global__ __launch_bounds__(640) void out_partial_kernel(
    const float* __restrict__ oW,
    const u64* __restrict__ fired,
    float* __restrict__ part, int lhstart, int partblock0) {
    int t = threadIdx.x;          // 0..639
    int b = t & 63;
    int c = t >> 6;
    int start = lhstart + blockIdx.x * LH_PER_BLOCK;
    float acc = 0.0f;
#pragma unroll 16
    for (int i = 0; i < LH_PER_BLOCK; i++) {
        int lh = start + i;
        u64 m = __ldg(&fired[lh]);
        float w = __ldg(&oW[lh * CC + c]);
        acc += w * (float)((m >> b) & 1ull);
    }
    part[(partblock0 + blockIdx.x) * (BB * CC) + t] = acc;
}

// Output stage 2: deterministic fixed-order reduction of partials.
__global__ void out_reduce_kernel(const float* __restrict__ part,
                                  float* __restrict__ out) {
    int t = threadIdx.x;
    if (t >= BB * CC) return;
    float s = 0.0f;
#pragma unroll
    for (int k = 0; k < OUT_BLOCKS; k++) s += part[k * (BB * CC) + t];
    int b = t & 63;
    int c = t >> 6;
    out[b * CC + c] = s;
}

// -------------------------------------------------------------------------
// Launch: ONE extraction stream at full grid width (co-running two extract
// grids measured 3.7 TB/s aggregate vs 4.8 TB/s for one full grid — R8-R15
// evidence), plus a side stream for the small latency-bound kernels.
//   origin: ex0(1024 blk) -> e0 -> ex1 -> e1 -> ex2 -> e2
//   s2:     encode -> [e0] fire0 -> [e1] fire1 -> out01 -> [e2] fire2
//           -> out2 -> reduce
// Tail after last extract = fire2 + out2 + reduce (~7us).
// Streams/events created ONCE on the first (pre-capture) call and reused —
// per-call creation leaked stream-pool memory past teardown (R10 fail).
// -------------------------------------------------------------------------
extern "C" void kernel_launch(void* const* d_in, const int* in_sizes, int n_in,
                              void* d_out, int out_size) {
    const float* x  = (const float*)d_in[0];
    const float* W0 = (const float*)d_in[1];
    const float* W1 = (const float*)d_in[2];
    const float* W2 = (const float*)d_in[3];
    const float* oW = (const float*)d_in[4];
    float* out = (float*)d_out;

    u64* act = nullptr;
    u64* fired = nullptr;
    float* part = nullptr;
    cudaGetSymbolAddress((void**)&act, g_act);
    cudaGetSymbolAddress((void**)&fired, g_fired);
    cudaGetSymbolAddress((void**)&part, g_part);

    static cudaStream_t s2 = nullptr;
    static cudaEvent_t eFork, e0, e1, e2, eDone;
    if (s2 == nullptr) {
        cudaStreamCreateWithFlags(&s2, cudaStreamNonBlocking);
        cudaEventCreateWithFlags(&eFork, cudaEventDisableTiming);
        cudaEventCreateWithFlags(&e0, cudaEventDisableTiming);
        cudaEventCreateWithFlags(&e1, cudaEventDisableTiming);
        cudaEventCreateWithFlags(&e2, cudaEventDisableTiming);
        cudaEventCreateWithFlags(&eDone, cudaEventDisableTiming);
    }

    // fork side stream into the capture
    cudaEventRecord(eFork, 0);
    cudaStreamWaitEvent(s2, eFork, 0);

    // s2: encode early (only gates fire0)
    encode_kernel<<<(P0 + 255) / 256, 256, 0, s2>>>(x);

    // origin stream: full-grid extracts, back-to-back
    extract_kernel<P0><<<1024, 256>>>(W0, 0);
    cudaEventRecord(e0, 0);
    extract_kernel<HN><<<1024, 256>>>(W1, SEGS_PER_LAYER);
    cudaEventRecord(e1, 0);
    extract_kernel<HN><<<1024, 256>>>(W2, 2 * SEGS_PER_LAYER);
    cudaEventRecord(e2, 0);

    // s2: fire chain + output, gated per layer; out01 hides under ex2
    cudaStreamWaitEvent(s2, e0, 0);
    fire_kernel<<<512, 256, 0, s2>>>(act, 0, fired);
    cudaStreamWaitEvent(s2, e1, 0);
    fire_kernel<<<512, 256, 0, s2>>>(fired, SEGS_PER_LAYER, fired + HN);
    out_partial_kernel<<<128, BB * CC, 0, s2>>>(oW, fired, part, 0, 0);
    cudaStreamWaitEvent(s2, e2, 0);
    fire_kernel<<<512, 256, 0, s2>>>(fired + HN, 2 * SEGS_PER_LAYER,
                                     fired + 2 * HN);
    out_partial_kernel<<<64, BB * CC, 0, s2>>>(oW, fired, part, 2 * HN, 128);
    out_reduce_kernel<<<1, BB * CC, 0, s2>>>(part, out);

    // join back into the origin stream (single graph sink)
    cudaEventRecord(eDone, s2);
    cudaStreamWaitEvent(0, eDone, 0);
}

// round 17
// speedup vs baseline: 1.2425x; 1.1740x over previous
#include <cuda_runtime.h>
#include <cstdint>

typedef unsigned long long u64;
typedef unsigned int u32;

#define NUM_BITS 16
#define THETA 8
#define HN 4096
#define FF 128
#define CC 10
#define BB 64
#define P0 2048                      // F*NUM_BITS
#define SEGS_PER_LAYER (2 * HN)      // 8192
#define TOT_SEGS (3 * SEGS_PER_LAYER)
#define MAXH 32

#define OUT_BLOCKS 192
#define LH_PER_BLOCK 64              // 12288 / 192

// Scratch (device globals: no allocation allowed in kernel_launch)
__device__ u64 g_act[P0];                 // layer-0 input masks
__device__ u64 g_fired[3 * HN];           // per-layer fired masks
__device__ u32 g_cnt[TOT_SEGS];           // entries per segment (<= 32)
__device__ u64 g_hits[TOT_SEGS * MAXH];   // packed: 4 x 16b (pos|sign|valid)
__device__ float g_part[OUT_BLOCKS * BB * CC];

// -------------------------------------------------------------------------
// Encode: x[B,F] -> g_act[p], p = f*16 + t, bit b = (x[b,f] >= (t+1)/17)
// -------------------------------------------------------------------------
__global__ void encode_kernel(const float* __restrict__ x) {
    int p = blockIdx.x * blockDim.x + threadIdx.x;
    if (p >= P0) return;
    int f = p >> 4;
    int t = p & 15;
    float thr = (float)(t + 1) / (float)(NUM_BITS + 1);
    u64 m = 0ull;
#pragma unroll
    for (int b = 0; b < BB; b++) {
        float v = __ldg(&x[b * FF + f]);
        m |= ((u64)(v >= thr)) << b;
    }
    g_act[p] = m;
}

// -------------------------------------------------------------------------
// Extract (R12 kernel, full-layer grid): one warp per SEGMENT. Rolling
// 8-deep uint4 pipeline. ONE ballot per 16B step: hitting lanes pack their
// component hits into a single u64 entry
//   field j (16b) = pos(12b) | signbit<<12 | valid<<13
// stored at base + popc(bal & ltmask). base advances warp-uniformly.
// Deterministic, no atomics. Entries per segment <= nonzeros <= 32.
// -------------------------------------------------------------------------
__device__ __forceinline__ u32 enc_hit(u32 wb, int p) {
    return wb ? ((u32)p | ((wb >> 31) << 12) | (1u << 13)) : 0u;
}

template <int P>
__global__ __launch_bounds__(256) void extract_kernel(
    const float* __restrict__ W, int segbase) {
    int seg = (blockIdx.x * blockDim.x + threadIdx.x) >> 5;   // 0..8191
    int lane = threadIdx.x & 31;
    u32 ltmask = (1u << lane) - 1u;

    const uint4* row = (const uint4*)(W + (size_t)seg * (size_t)P);
    u64* hp = &g_hits[(size_t)(segbase + seg) * MAXH];
    int base = 0;

    constexpr int NS = P / 128;       // uint4 steps per lane: 16 or 32
    uint4 v[8];
#pragma unroll
    for (int k = 0; k < 8; k++)
        v[k] = __ldg(&row[k * 32 + lane]);

#pragma unroll
    for (int i = 0; i < NS; i++) {
        uint4 w = v[i & 7];
        if (i + 8 < NS)                       // refill slot behind processing
            v[i & 7] = __ldg(&row[(i + 8) * 32 + lane]);

        u32 any = (w.x | w.y) | (w.z | w.w);
        u32 bal = __ballot_sync(0xffffffffu, any != 0u);
        if (bal) {                            // warp-uniform branch
            if (any) {                        // ~1 lane per step
                int p = (i * 32 + lane) * 4;
                u64 e = (u64)enc_hit(w.x, p)
                      | ((u64)enc_hit(w.y, p + 1) << 16)
                      | ((u64)enc_hit(w.z, p + 2) << 32)
                      | ((u64)enc_hit(w.w, p + 3) << 48);
                int s = base + __popc(bal & ltmask);
                if (s < MAXH) hp[s] = e;
            }
            base += __popc(bal);
        }
    }
    if (lane == 0)
        g_cnt[segbase + seg] = (u32)(base > MAXH ? MAXH : base);
}

// -------------------------------------------------------------------------
// Fire (R12): one warp per NEURON. Lane k loads packed entry k of each
// segment (parallel). Decodes <=4 sub-hits, accumulates +-act masks into
// 7-plane signed bit-sliced counters (two's complement, bounded +-32 ->
// exact). One 5-round butterfly per segment; fired iff count>=8 (sign
// clear and any of bits 3..5). Deterministic.
// -------------------------------------------------------------------------
__device__ __forceinline__ void acc_entry(u64 e, const u64* __restrict__ act,
                                          u64* c) {
#pragma unroll
    for (int j = 0; j < 4; j++) {
        u32 f = (u32)(e >> (16 * j)) & 0xFFFFu;
        if (f & (1u << 13)) {
            u64 m = __ldg(&act[f & 0xFFFu]);
            u64 neg = (f & (1u << 12)) ? ~0ull : 0ull;
            u64 a = m, carry = 0;
#pragma unroll
            for (int k = 0; k < 7; k++) {
                u64 ck = c[k];
                u64 x = ck ^ a;
                c[k] = x ^ carry;
                carry = (ck & a) | (carry & x);
                a = m & neg;   // planes 1..6: 0 for +1, m for -1
            }
        }
    }
}

__device__ __forceinline__ u64 reduce_fire(u64* c) {
#pragma unroll
    for (int off = 16; off > 0; off >>= 1) {
        u64 t[7];
#pragma unroll
        for (int k = 0; k < 7; k++)
            t[k] = __shfl_xor_sync(0xffffffffu, c[k], off);
        u64 carry = 0;
#pragma unroll
        for (int k = 0; k < 7; k++) {
            u64 ck = c[k], bk = t[k];
            u64 x = ck ^ bk;
            c[k] = x ^ carry;
            carry = (ck & bk) | (carry & x);
        }
    }
    return ~c[6] & (c[3] | c[4] | c[5]);
}

__global__ __launch_bounds__(256) void fire_kernel(
    const u64* __restrict__ act, int segbase, u64* __restrict__ fired) {
    int h = (blockIdx.x * blockDim.x + threadIdx.x) >> 5;
    int lane = threadIdx.x & 31;
    if (h >= HN) return;

    int seg0 = segbase + 2 * h;
    int n0 = (int)g_cnt[seg0];
    int n1 = (int)g_cnt[seg0 + 1];

    u64 e0 = (lane < n0) ? __ldg(&g_hits[(size_t)seg0 * MAXH + lane]) : 0ull;
    u64 e1 = (lane < n1) ? __ldg(&g_hits[(size_t)(seg0 + 1) * MAXH + lane])
                         : 0ull;

    u64 c[7] = {0, 0, 0, 0, 0, 0, 0};
    acc_entry(e0, act, c);
    u64 fm = reduce_fire(c);
#pragma unroll
    for (int k = 0; k < 7; k++) c[k] = 0ull;
    acc_entry(e1, act, c);
    fm |= reduce_fire(c);

    if (lane == 0) fired[h] = fm;
}

// -------------------------------------------------------------------------
// Output stage 1: partial sums over (l,h) slices.
// -------------------------------------------------------------------------
__global__ __launch_bounds__(640) void out_partial_kernel(
    const float* __restrict__ oW,
    const u64* __restrict__ fired,
    float* __restrict__ part) {
    int t = threadIdx.x;          // 0..639
    int b = t & 63;
    int c = t >> 6;
    int start = blockIdx.x * LH_PER_BLOCK;
    float acc = 0.0f;
#pragma unroll 16
    for (int i = 0; i < LH_PER_BLOCK; i++) {
        int lh = start + i;       // flat l*H + h
        u64 m = __ldg(&fired[lh]);
        float w = __ldg(&oW[lh * CC + c]);
        acc += w * (float)((m >> b) & 1ull);
    }
    part[blockIdx.x * (BB * CC) + t] = acc;
}

// Output stage 2: deterministic fixed-order reduction of partials.
__global__ void out_reduce_kernel(const float* __restrict__ part,
                                  float* __restrict__ out) {
    int t = threadIdx.x;
    if (t >= BB * CC) return;
    float s = 0.0f;
#pragma unroll
    for (int k = 0; k < OUT_BLOCKS; k++) s += part[k * (BB * CC) + t];
    int b = t & 63;
    int c = t >> 6;
    out[b * CC + c] = s;
}

// -------------------------------------------------------------------------
// Launch: FULLY SERIAL single stream. R8-R16 evidence: co-running anything
// against the extract stream costs more extraction bandwidth than the
// overlapped work saves (R16: serial extracts + side-stream fires = 139us
// vs R8 fully-serial 123us; R12's 102.8 was carried by its cheaper fire,
// not the overlap). Extraction runs alone at its best measured rate
// (~4.8TB/s); each fire runs immediately after its extract so the 5MB hit
// list is still L2-hot. No streams, no events.
// -------------------------------------------------------------------------
extern "C" void kernel_launch(void* const* d_in, const int* in_sizes, int n_in,
                              void* d_out, int out_size) {
    const float* x  = (const float*)d_in[0];
    const float* W0 = (const float*)d_in[1];
    const float* W1 = (const float*)d_in[2];
    const float* W2 = (const float*)d_in[3];
    const float* oW = (const float*)d_in[4];
    float* out = (float*)d_out;

    u64* act = nullptr;
    u64* fired = nullptr;
    float* part = nullptr;
    cudaGetSymbolAddress((void**)&act, g_act);
    cudaGetSymbolAddress((void**)&fired, g_fired);
    cudaGetSymbolAddress((void**)&part, g_part);

    encode_kernel<<<(P0 + 255) / 256, 256>>>(x);

    extract_kernel<P0><<<1024, 256>>>(W0, 0);
    fire_kernel<<<512, 256>>>(act, 0, fired);

    extract_kernel<HN><<<1024, 256>>>(W1, SEGS_PER_LAYER);
    fire_kernel<<<512, 256>>>(fired, SEGS_PER_LAYER, fired + HN);

    extract_kernel<HN><<<1024, 256>>>(W2, 2 * SEGS_PER_LAYER);
    fire_kernel<<<512, 256>>>(fired + HN, 2 * SEGS_PER_LAYER,
                              fired + 2 * HN);

    out_partial_kernel<<<OUT_BLOCKS, BB * CC>>>(oW, fired, part);
    out_reduce_kernel<<<1, BB * CC>>>(part, out);
}